// round 4
// baseline (speedup 1.0000x reference)
#include <cuda_runtime.h>
#include <cuda_bf16.h>
#include <cstdint>

#define B_    64
#define Himg  56
#define Wimg  56
#define C_    128
#define N_    3136
#define NHEAD 4
#define M_TOT (B_ * N_)     // 200704

// Scratch (allocation-free rule: device globals)
__device__ float g_qkv[(size_t)M_TOT * 384];           // 308 MB
__device__ float g_attn[(size_t)M_TOT * C_];           // 103 MB
__device__ __nv_bfloat16 g_wh[512 * 128];              // weights hi (qkv rows 0..383, proj 384..511)
__device__ __nv_bfloat16 g_wl[512 * 128];              // weights lo

// ============================================================================
// Weight split prep: fp32 -> bf16 hi/lo
// ============================================================================
__global__ void prep_weights(const float* __restrict__ w_qkv,
                             const float* __restrict__ w_proj)
{
    int idx = blockIdx.x * 256 + threadIdx.x;
    if (idx >= 512 * 128) return;
    float w = (idx < 384 * 128) ? w_qkv[idx] : w_proj[idx - 384 * 128];
    __nv_bfloat16 hi = __float2bfloat16(w);
    float r = w - __bfloat162float(hi);
    g_wh[idx] = hi;
    g_wl[idx] = __float2bfloat16(r);
}

// ============================================================================
// HMMA GEMM: C[M, ldc] = A[M,128] @ W[N,128]^T (+bias), 3-term bf16 split.
// Tile 128x128, 256 threads (8 warps, 4x2), warp tile 32x64.
// A tile loaded+split ONCE; loops over ntiles W tiles (N = ntiles*128).
// ============================================================================
#define LDT 136                      // padded row stride in bf16 elements
#define TILE_B (128 * LDT * 2)       // 34816 B per tile
#define SM_AHI 0
#define SM_ALO (TILE_B)
#define SM_WHI (2 * TILE_B)
#define SM_WLO (3 * TILE_B)
#define SM_BYTES (4 * TILE_B)

__device__ __forceinline__ uint32_t smem_u32(const void* p) {
    uint32_t a;
    asm("{ .reg .u64 t; cvta.to.shared.u64 t, %1; cvt.u32.u64 %0, t; }" : "=r"(a) : "l"(p));
    return a;
}

__device__ __forceinline__ uint32_t pack2(float a, float b) {
    __nv_bfloat16 ha = __float2bfloat16(a), hb = __float2bfloat16(b);
    unsigned short ua = reinterpret_cast<unsigned short&>(ha);
    unsigned short ub = reinterpret_cast<unsigned short&>(hb);
    return (uint32_t)ua | ((uint32_t)ub << 16);
}

__device__ __forceinline__ void mma16816(float* d, const uint32_t* a, const uint32_t* b) {
    asm volatile(
        "mma.sync.aligned.m16n8k16.row.col.f32.bf16.bf16.f32 "
        "{%0,%1,%2,%3}, {%4,%5,%6,%7}, {%8,%9}, {%0,%1,%2,%3};"
        : "+f"(d[0]), "+f"(d[1]), "+f"(d[2]), "+f"(d[3])
        : "r"(a[0]), "r"(a[1]), "r"(a[2]), "r"(a[3]), "r"(b[0]), "r"(b[1]));
}

__global__ void __launch_bounds__(256)
hmma_gemm(const float* __restrict__ A,
          const __nv_bfloat16* __restrict__ whi,
          const __nv_bfloat16* __restrict__ wlo,
          float* __restrict__ C, int ldc, int ntiles,
          const float* __restrict__ bias)
{
    extern __shared__ char smem[];
    const uint32_t sb = smem_u32(smem);
    const int tid = threadIdx.x;
    const int wid = tid >> 5;
    const int lane = tid & 31;
    const int m0 = blockIdx.x * 128;

    // ---- Load + split A tile (128 x 128 fp32 -> bf16 hi/lo), once ----
#pragma unroll
    for (int it = 0; it < 8; it++) {
        int e = it * 256 + tid;
        int r = e >> 4;
        int k0 = (e & 15) * 8;
        const float4* p = reinterpret_cast<const float4*>(A + (size_t)(m0 + r) * 128 + k0);
        float4 x0 = p[0], x1 = p[1];
        float f[8] = {x0.x, x0.y, x0.z, x0.w, x1.x, x1.y, x1.z, x1.w};
        uint32_t h[4], l[4];
#pragma unroll
        for (int j = 0; j < 4; j++) {
            float a = f[2 * j], b = f[2 * j + 1];
            __nv_bfloat16 ha = __float2bfloat16(a), hb = __float2bfloat16(b);
            float ra = a - __bfloat162float(ha);
            float rb = b - __bfloat162float(hb);
            unsigned short ua = reinterpret_cast<unsigned short&>(ha);
            unsigned short ub = reinterpret_cast<unsigned short&>(hb);
            h[j] = (uint32_t)ua | ((uint32_t)ub << 16);
            l[j] = pack2(ra, rb);
        }
        uint32_t off = (uint32_t)(r * LDT + k0) * 2;
        *reinterpret_cast<uint4*>(smem + SM_AHI + off) = make_uint4(h[0], h[1], h[2], h[3]);
        *reinterpret_cast<uint4*>(smem + SM_ALO + off) = make_uint4(l[0], l[1], l[2], l[3]);
    }

    const int mrow = (wid & 3) * 32;
    const int ncol = (wid >> 2) * 64;
    const int grp = lane >> 2;
    const int thr4 = lane & 3;

    for (int nt = 0; nt < ntiles; nt++) {
        const int n0 = nt * 128;
        // ---- Load W tiles for this n block ----
#pragma unroll
        for (int it = 0; it < 8; it++) {
            int e = it * 256 + tid;
            int r = e >> 4;
            int k0 = (e & 15) * 8;
            uint32_t off = (uint32_t)(r * LDT + k0) * 2;
            *reinterpret_cast<uint4*>(smem + SM_WHI + off) =
                *reinterpret_cast<const uint4*>(whi + (size_t)(n0 + r) * 128 + k0);
            *reinterpret_cast<uint4*>(smem + SM_WLO + off) =
                *reinterpret_cast<const uint4*>(wlo + (size_t)(n0 + r) * 128 + k0);
        }
        __syncthreads();

        float acc[2][8][4];
#pragma unroll
        for (int mt = 0; mt < 2; mt++)
#pragma unroll
            for (int ntt = 0; ntt < 8; ntt++)
#pragma unroll
                for (int j = 0; j < 4; j++) acc[mt][ntt][j] = 0.f;

#pragma unroll
        for (int pass = 0; pass < 3; pass++) {
            const uint32_t sA = sb + ((pass == 2) ? SM_ALO : SM_AHI);
            const uint32_t sB = sb + ((pass == 1) ? SM_WLO : SM_WHI);
#pragma unroll
            for (int ks = 0; ks < 8; ks++) {
                const int k0 = ks * 16;
                uint32_t afr[2][4];
#pragma unroll
                for (int mt = 0; mt < 2; mt++) {
                    int r = mrow + mt * 16 + grp;
                    uint32_t base = sA + (uint32_t)(r * LDT + k0 + thr4 * 2) * 2;
                    asm volatile("ld.shared.b32 %0, [%1];" : "=r"(afr[mt][0]) : "r"(base));
                    asm volatile("ld.shared.b32 %0, [%1];" : "=r"(afr[mt][1]) : "r"(base + 8 * LDT * 2));
                    asm volatile("ld.shared.b32 %0, [%1];" : "=r"(afr[mt][2]) : "r"(base + 16));
                    asm volatile("ld.shared.b32 %0, [%1];" : "=r"(afr[mt][3]) : "r"(base + 8 * LDT * 2 + 16));
                }
#pragma unroll
                for (int ntt = 0; ntt < 8; ntt++) {
                    int n = ncol + ntt * 8 + grp;
                    uint32_t base = sB + (uint32_t)(n * LDT + k0 + thr4 * 2) * 2;
                    uint32_t bfr[2];
                    asm volatile("ld.shared.b32 %0, [%1];" : "=r"(bfr[0]) : "r"(base));
                    asm volatile("ld.shared.b32 %0, [%1];" : "=r"(bfr[1]) : "r"(base + 16));
#pragma unroll
                    for (int mt = 0; mt < 2; mt++)
                        mma16816(acc[mt][ntt], afr[mt], bfr);
                }
            }
        }

        // ---- Epilogue ----
#pragma unroll
        for (int mt = 0; mt < 2; mt++) {
            int r0 = m0 + mrow + mt * 16 + grp;
#pragma unroll
            for (int ntt = 0; ntt < 8; ntt++) {
                int c = n0 + ncol + ntt * 8 + thr4 * 2;
                float bx = 0.f, by = 0.f;
                if (bias) { bx = bias[c]; by = bias[c + 1]; }
                float2 v0 = make_float2(acc[mt][ntt][0] + bx, acc[mt][ntt][1] + by);
                float2 v1 = make_float2(acc[mt][ntt][2] + bx, acc[mt][ntt][3] + by);
                *reinterpret_cast<float2*>(C + (size_t)r0 * ldc + c) = v0;
                *reinterpret_cast<float2*>(C + (size_t)(r0 + 8) * ldc + c) = v1;
            }
        }
        __syncthreads();
    }
}

// ============================================================================
// Fused windowed attention + depthwise conv + bias.
// One block per (batch, window): 256 threads, all 4 heads.
// v loaded with 9x9 halo so the 3x3 depthwise conv is applied at output write.
// ============================================================================
// smem layout (floats):
//  qs: 4*52*33 = 6864     ks: 6864
//  vs: 4*81*33 = 10692    S : 4*52*52 = 10816
//  wlm: 1152 (128*9)      blm: 128
#define ATT_QS   0
#define ATT_KS   (4 * 52 * 33)
#define ATT_VS   (2 * 4 * 52 * 33)
#define ATT_S    (ATT_VS + 4 * 81 * 33)
#define ATT_WLM  (ATT_S + 4 * 52 * 52)
#define ATT_BLM  (ATT_WLM + 128 * 9)
#define ATT_FLOATS (ATT_BLM + 128)
#define ATT_BYTES (ATT_FLOATS * 4)

__global__ __launch_bounds__(256) void attn_fused(
    const float* __restrict__ w_lim, const float* __restrict__ b_lim)
{
    extern __shared__ float sm[];
    float* qs = sm + ATT_QS;
    float* ks = sm + ATT_KS;
    float* vs = sm + ATT_VS;
    float* S  = sm + ATT_S;
    float* wlm = sm + ATT_WLM;
    float* blm = sm + ATT_BLM;

    const int gb = blockIdx.x;
    const int g = gb & 63, b = gb >> 6;
    const int gy = g >> 3, gx = g & 7;
    const int Y0 = gy * 7, X0 = gx * 7;
    const int tid = threadIdx.x;

    // conv weights + bias into smem
    for (int l = tid; l < 128 * 9; l += 256) wlm[l] = w_lim[l];
    if (tid < 128) blm[tid] = b_lim[tid];

    // load q, k (49 tokens x 128 ch, coalesced)
    for (int l = tid; l < 49 * 128; l += 256) {
        int i = l >> 7, c = l & 127;
        int h = c >> 5, cc = c & 31;
        int n = (Y0 + i / 7) * 56 + X0 + (i % 7);
        size_t base = ((size_t)b * N_ + n) * 384 + c;
        qs[(h * 52 + i) * 33 + cc] = g_qkv[base];
        ks[(h * 52 + i) * 33 + cc] = g_qkv[base + 128];
    }
    // zero pad rows 49..51
    for (int l = tid; l < 4 * 3 * 32; l += 256) {
        int h = l / 96, r = 49 + (l % 96) / 32, cc = l & 31;
        qs[(h * 52 + r) * 33 + cc] = 0.f;
        ks[(h * 52 + r) * 33 + cc] = 0.f;
    }
    // load v with 9x9 halo (zero outside image)
    for (int l = tid; l < 81 * 128; l += 256) {
        int j = l >> 7, c = l & 127;
        int h = c >> 5, cc = c & 31;
        int Y = Y0 + j / 9 - 1, X = X0 + j % 9 - 1;
        float v = 0.f;
        if ((unsigned)Y < 56u && (unsigned)X < 56u)
            v = g_qkv[((size_t)b * N_ + Y * 56 + X) * 384 + 256 + c];
        vs[(h * 81 + j) * 33 + cc] = v;
    }
    __syncthreads();

    const float scale = 0.17677669529663687f;   // 32^-0.5

    // ---- S = scale * q @ k^T : 4 heads x 169 tiles of 4x4 ----
    for (int t = tid; t < 676; t += 256) {
        int h = t / 169, tt = t % 169;
        int ti = (tt / 13) * 4, tj = (tt % 13) * 4;
        const float* qh = qs + (h * 52) * 33;
        const float* kh = ks + (h * 52) * 33;
        float acc[4][4];
#pragma unroll
        for (int ii = 0; ii < 4; ii++)
#pragma unroll
            for (int jj = 0; jj < 4; jj++) acc[ii][jj] = 0.f;
#pragma unroll
        for (int c = 0; c < 32; c++) {
            float a[4], bb[4];
#pragma unroll
            for (int ii = 0; ii < 4; ii++) a[ii] = qh[(ti + ii) * 33 + c];
#pragma unroll
            for (int jj = 0; jj < 4; jj++) bb[jj] = kh[(tj + jj) * 33 + c];
#pragma unroll
            for (int ii = 0; ii < 4; ii++)
#pragma unroll
                for (int jj = 0; jj < 4; jj++) acc[ii][jj] += a[ii] * bb[jj];
        }
        float* Sh = S + (h * 52) * 52;
#pragma unroll
        for (int ii = 0; ii < 4; ii++)
#pragma unroll
            for (int jj = 0; jj < 4; jj++)
                Sh[(ti + ii) * 52 + tj + jj] = acc[ii][jj] * scale;
    }
    __syncthreads();

    // ---- softmax: 4 heads x 49 rows ----
    for (int t = tid; t < 196; t += 256) {
        int h = t / 49, r = t % 49;
        float* row = S + (h * 52 + r) * 52;
        float m = -1e30f;
        for (int j = 0; j < 49; j++) m = fmaxf(m, row[j]);
        float s = 0.f;
        for (int j = 0; j < 49; j++) {
            float e = __expf(row[j] - m);
            row[j] = e;
            s += e;
        }
        float inv = __fdividef(1.f, s);
        for (int j = 0; j < 49; j++) row[j] *= inv;
    }
    __syncthreads();

    // ---- O = P @ v (+ conv(v) + bias) : 4 heads x 13 x 8 tiles of 4x4 ----
    for (int t = tid; t < 416; t += 256) {
        int h = t / 104, tt = t % 104;
        int ti = (tt >> 3) * 4, td = (tt & 7) * 4;
        const float* Sh = S + (h * 52) * 52;
        const float* vh = vs + (h * 81) * 33;
        float acc[4][4];
#pragma unroll
        for (int ii = 0; ii < 4; ii++)
#pragma unroll
            for (int dd = 0; dd < 4; dd++) acc[ii][dd] = 0.f;
#pragma unroll
        for (int jy = 0; jy < 7; jy++)
#pragma unroll
            for (int jx = 0; jx < 7; jx++) {
                int j = jy * 7 + jx;
                const float* vp = vh + ((jy + 1) * 9 + jx + 1) * 33 + td;
                float p[4], v[4];
#pragma unroll
                for (int ii = 0; ii < 4; ii++) p[ii] = Sh[(ti + ii) * 52 + j];
#pragma unroll
                for (int dd = 0; dd < 4; dd++) v[dd] = vp[dd];
#pragma unroll
                for (int ii = 0; ii < 4; ii++)
#pragma unroll
                    for (int dd = 0; dd < 4; dd++) acc[ii][dd] += p[ii] * v[dd];
            }
#pragma unroll
        for (int ii = 0; ii < 4; ii++) {
            int i = ti + ii;
            if (i < 49) {
                int iy = i / 7, ix = i % 7;
                int n = (Y0 + iy) * 56 + X0 + ix;
                size_t ob = ((size_t)b * N_ + n) * 128 + h * 32 + td;
#pragma unroll
                for (int dd = 0; dd < 4; dd++) {
                    int c = h * 32 + td + dd;
                    // depthwise 3x3 conv from halo'd v + bias
                    float s = blm[c];
                    const float* wl = wlm + c * 9;
#pragma unroll
                    for (int dy = 0; dy < 3; dy++)
#pragma unroll
                        for (int dx = 0; dx < 3; dx++)
                            s += wl[dy * 3 + dx] *
                                 vh[((iy + dy) * 9 + (ix + dx)) * 33 + td + dd];
                    g_attn[ob + dd] = acc[ii][dd] + s;
                }
            }
        }
    }
}

// ============================================================================
extern "C" void kernel_launch(void* const* d_in, const int* in_sizes, int n_in,
                              void* d_out, int out_size)
{
    const float* x      = (const float*)d_in[0];
    const float* w_qkv  = (const float*)d_in[1];
    const float* w_lim  = (const float*)d_in[2];
    const float* b_lim  = (const float*)d_in[3];
    const float* w_proj = (const float*)d_in[4];
    const float* b_proj = (const float*)d_in[5];
    float* out = (float*)d_out;

    float *qkv_ptr, *attn_ptr;
    __nv_bfloat16 *wh_ptr, *wl_ptr;
    cudaGetSymbolAddress((void**)&qkv_ptr,  g_qkv);
    cudaGetSymbolAddress((void**)&attn_ptr, g_attn);
    cudaGetSymbolAddress((void**)&wh_ptr,   g_wh);
    cudaGetSymbolAddress((void**)&wl_ptr,   g_wl);

    cudaFuncSetAttribute(hmma_gemm, cudaFuncAttributeMaxDynamicSharedMemorySize, SM_BYTES);
    cudaFuncSetAttribute(attn_fused, cudaFuncAttributeMaxDynamicSharedMemorySize, ATT_BYTES);

    // 0) split weights into bf16 hi/lo
    prep_weights<<<(512 * 128 + 255) / 256, 256>>>(w_qkv, w_proj);

    // 1) qkv = x @ w_qkv^T  (A tile loaded once, 3 W tiles)
    hmma_gemm<<<M_TOT / 128, 256, SM_BYTES>>>(x, wh_ptr, wl_ptr, qkv_ptr, 384, 3, nullptr);

    // 2) fused windowed attention + depthwise conv + bias
    attn_fused<<<B_ * 64, 256, ATT_BYTES>>>(w_lim, b_lim);

    // 3) out = g_attn @ w_proj^T + b_proj
    hmma_gemm<<<M_TOT / 128, 256, SM_BYTES>>>(attn_ptr, wh_ptr + 384 * 128,
                                              wl_ptr + 384 * 128, out, 128, 1, b_proj);
}

// round 6
// speedup vs baseline: 1.0030x; 1.0030x over previous
#include <cuda_runtime.h>
#include <cuda_bf16.h>
#include <cstdint>

#define B_    64
#define Himg  56
#define Wimg  56
#define C_    128
#define N_    3136
#define NHEAD 4
#define M_TOT (B_ * N_)     // 200704

// Scratch (allocation-free rule: device globals)
__device__ float g_qkv[(size_t)M_TOT * 384];           // 308 MB
__device__ float g_attn[(size_t)M_TOT * C_];           // 103 MB
__device__ __nv_bfloat16 g_wh[512 * 128];              // weights hi (qkv rows 0..383, proj 384..511)
__device__ __nv_bfloat16 g_wl[512 * 128];              // weights lo

// ============================================================================
// Weight split prep: fp32 -> bf16 hi/lo
// ============================================================================
__global__ void prep_weights(const float* __restrict__ w_qkv,
                             const float* __restrict__ w_proj)
{
    int idx = blockIdx.x * 256 + threadIdx.x;
    if (idx >= 512 * 128) return;
    float w = (idx < 384 * 128) ? w_qkv[idx] : w_proj[idx - 384 * 128];
    __nv_bfloat16 hi = __float2bfloat16(w);
    float r = w - __bfloat162float(hi);
    g_wh[idx] = hi;
    g_wl[idx] = __float2bfloat16(r);
}

// ============================================================================
// HMMA GEMM: C[M, ldc] = A[M,128] @ W[N,128]^T (+bias), 3-term bf16 split.
// CTA tile 64x128, 256 threads (8 warps: 2 along M x 4 along N), warp 32x32.
// A tile loaded+split ONCE; loops over ntiles W tiles. 2 CTAs/SM.
// ============================================================================
#define LDT 136                          // padded row stride (bf16 elems)
#define SM_AHI 0
#define SM_ALO (64 * LDT * 2)            // 17408
#define SM_WHI (2 * 64 * LDT * 2)        // 34816
#define SM_WLO (SM_WHI + 128 * LDT * 2)  // 69632
#define SM_BYTES (SM_WLO + 128 * LDT * 2) // 104448

__device__ __forceinline__ uint32_t smem_u32(const void* p) {
    uint32_t a;
    asm("{ .reg .u64 t; cvta.to.shared.u64 t, %1; cvt.u32.u64 %0, t; }" : "=r"(a) : "l"(p));
    return a;
}

__device__ __forceinline__ uint32_t pack2(float a, float b) {
    __nv_bfloat16 ha = __float2bfloat16(a), hb = __float2bfloat16(b);
    unsigned short ua = reinterpret_cast<unsigned short&>(ha);
    unsigned short ub = reinterpret_cast<unsigned short&>(hb);
    return (uint32_t)ua | ((uint32_t)ub << 16);
}

__device__ __forceinline__ void mma16816(float* d, const uint32_t* a, const uint32_t* b) {
    asm volatile(
        "mma.sync.aligned.m16n8k16.row.col.f32.bf16.bf16.f32 "
        "{%0,%1,%2,%3}, {%4,%5,%6,%7}, {%8,%9}, {%0,%1,%2,%3};"
        : "+f"(d[0]), "+f"(d[1]), "+f"(d[2]), "+f"(d[3])
        : "r"(a[0]), "r"(a[1]), "r"(a[2]), "r"(a[3]), "r"(b[0]), "r"(b[1]));
}

__global__ void __launch_bounds__(256, 2)
hmma_gemm(const float* __restrict__ A,
          const __nv_bfloat16* __restrict__ whi,
          const __nv_bfloat16* __restrict__ wlo,
          float* __restrict__ C, int ldc, int ntiles,
          const float* __restrict__ bias)
{
    extern __shared__ char smem[];
    const uint32_t sb = smem_u32(smem);
    const int tid = threadIdx.x;
    const int wid = tid >> 5;
    const int lane = tid & 31;
    const int m0 = blockIdx.x * 64;

    // ---- Load + split A tile (64 x 128 fp32 -> bf16 hi/lo), once ----
#pragma unroll
    for (int it = 0; it < 4; it++) {
        int e = it * 256 + tid;          // 1024 chunks of 8 k-cols
        int r = e >> 4;
        int k0 = (e & 15) * 8;
        const float4* p = reinterpret_cast<const float4*>(A + (size_t)(m0 + r) * 128 + k0);
        float4 x0 = p[0], x1 = p[1];
        float f[8] = {x0.x, x0.y, x0.z, x0.w, x1.x, x1.y, x1.z, x1.w};
        uint32_t h[4], l[4];
#pragma unroll
        for (int j = 0; j < 4; j++) {
            float a = f[2 * j], b = f[2 * j + 1];
            __nv_bfloat16 ha = __float2bfloat16(a), hb = __float2bfloat16(b);
            float ra = a - __bfloat162float(ha);
            float rb = b - __bfloat162float(hb);
            unsigned short ua = reinterpret_cast<unsigned short&>(ha);
            unsigned short ub = reinterpret_cast<unsigned short&>(hb);
            h[j] = (uint32_t)ua | ((uint32_t)ub << 16);
            l[j] = pack2(ra, rb);
        }
        uint32_t off = (uint32_t)(r * LDT + k0) * 2;
        *reinterpret_cast<uint4*>(smem + SM_AHI + off) = make_uint4(h[0], h[1], h[2], h[3]);
        *reinterpret_cast<uint4*>(smem + SM_ALO + off) = make_uint4(l[0], l[1], l[2], l[3]);
    }

    const int mrow = (wid & 1) * 32;       // 2 warps along M
    const int ncol = (wid >> 1) * 32;      // 4 warps along N
    const int grp = lane >> 2;
    const int thr4 = lane & 3;

    for (int nt = 0; nt < ntiles; nt++) {
        const int n0 = nt * 128;
#pragma unroll
        for (int it = 0; it < 8; it++) {
            int e = it * 256 + tid;
            int r = e >> 4;
            int k0 = (e & 15) * 8;
            uint32_t off = (uint32_t)(r * LDT + k0) * 2;
            *reinterpret_cast<uint4*>(smem + SM_WHI + off) =
                *reinterpret_cast<const uint4*>(whi + (size_t)(n0 + r) * 128 + k0);
            *reinterpret_cast<uint4*>(smem + SM_WLO + off) =
                *reinterpret_cast<const uint4*>(wlo + (size_t)(n0 + r) * 128 + k0);
        }
        __syncthreads();

        float acc[2][4][4];
#pragma unroll
        for (int mt = 0; mt < 2; mt++)
#pragma unroll
            for (int ntt = 0; ntt < 4; ntt++)
#pragma unroll
                for (int j = 0; j < 4; j++) acc[mt][ntt][j] = 0.f;

#pragma unroll
        for (int pass = 0; pass < 3; pass++) {
            const uint32_t sA = sb + ((pass == 2) ? SM_ALO : SM_AHI);
            const uint32_t sB = sb + ((pass == 1) ? SM_WLO : SM_WHI);
#pragma unroll
            for (int ks = 0; ks < 8; ks++) {
                const int k0 = ks * 16;
                uint32_t afr[2][4];
#pragma unroll
                for (int mt = 0; mt < 2; mt++) {
                    int r = mrow + mt * 16 + grp;
                    uint32_t base = sA + (uint32_t)(r * LDT + k0 + thr4 * 2) * 2;
                    asm volatile("ld.shared.b32 %0, [%1];" : "=r"(afr[mt][0]) : "r"(base));
                    asm volatile("ld.shared.b32 %0, [%1];" : "=r"(afr[mt][1]) : "r"(base + 8 * LDT * 2));
                    asm volatile("ld.shared.b32 %0, [%1];" : "=r"(afr[mt][2]) : "r"(base + 16));
                    asm volatile("ld.shared.b32 %0, [%1];" : "=r"(afr[mt][3]) : "r"(base + 8 * LDT * 2 + 16));
                }
#pragma unroll
                for (int ntt = 0; ntt < 4; ntt++) {
                    int n = ncol + ntt * 8 + grp;
                    uint32_t base = sB + (uint32_t)(n * LDT + k0 + thr4 * 2) * 2;
                    uint32_t bfr[2];
                    asm volatile("ld.shared.b32 %0, [%1];" : "=r"(bfr[0]) : "r"(base));
                    asm volatile("ld.shared.b32 %0, [%1];" : "=r"(bfr[1]) : "r"(base + 16));
#pragma unroll
                    for (int mt = 0; mt < 2; mt++)
                        mma16816(acc[mt][ntt], afr[mt], bfr);
                }
            }
        }

        // ---- Epilogue ----
#pragma unroll
        for (int mt = 0; mt < 2; mt++) {
            int r0 = m0 + mrow + mt * 16 + grp;
#pragma unroll
            for (int ntt = 0; ntt < 4; ntt++) {
                int c = n0 + ncol + ntt * 8 + thr4 * 2;
                float bx = 0.f, by = 0.f;
                if (bias) { bx = bias[c]; by = bias[c + 1]; }
                float2 v0 = make_float2(acc[mt][ntt][0] + bx, acc[mt][ntt][1] + by);
                float2 v1 = make_float2(acc[mt][ntt][2] + bx, acc[mt][ntt][3] + by);
                *reinterpret_cast<float2*>(C + (size_t)r0 * ldc + c) = v0;
                *reinterpret_cast<float2*>(C + (size_t)(r0 + 8) * ldc + c) = v1;
            }
        }
        __syncthreads();
    }
}

// ============================================================================
// Fused windowed attention + depthwise conv: one block per (b, window, head).
// 224 threads. smem ~36.6 KB -> ~6 CTAs/SM. v loaded with 9x9 halo.
// ============================================================================
__global__ __launch_bounds__(224) void attn_fused(
    const float* __restrict__ w_lim, const float* __restrict__ b_lim)
{
    const int idx = blockIdx.x;
    const int h = idx & 3;
    const int g = (idx >> 2) & 63;
    const int b = idx >> 8;
    const int gy = g >> 3, gx = g & 7;
    const int Y0 = gy * 7, X0 = gx * 7;

    __shared__ float qs[52][33];
    __shared__ float ks[52][33];
    __shared__ float vs[81][33];
    __shared__ float S[52 * 52];
    __shared__ float wl[32 * 9];
    __shared__ float bl[32];

    const int tid = threadIdx.x;

    // conv weights/bias for this head's 32 channels (288 > blockDim: strided!)
    for (int l = tid; l < 288; l += 224) wl[l] = w_lim[h * 32 * 9 + l];
    if (tid < 32) bl[tid] = b_lim[h * 32 + tid];

    // load q, k (49 x 32)
    for (int l = tid; l < 49 * 32; l += 224) {
        int i = l >> 5, c = l & 31;
        int n = (Y0 + i / 7) * 56 + X0 + (i % 7);
        size_t base = ((size_t)b * N_ + n) * 384 + h * 32 + c;
        qs[i][c] = g_qkv[base];
        ks[i][c] = g_qkv[base + 128];
    }
    if (tid < 96) {
        int r = 49 + tid / 32, c = tid & 31;
        qs[r][c] = 0.f; ks[r][c] = 0.f;
    }
    // load v with 9x9 halo (zero outside image)
    for (int l = tid; l < 81 * 32; l += 224) {
        int j = l >> 5, c = l & 31;
        int Y = Y0 + j / 9 - 1, X = X0 + j % 9 - 1;
        float v = 0.f;
        if ((unsigned)Y < 56u && (unsigned)X < 56u)
            v = g_qkv[((size_t)b * N_ + Y * 56 + X) * 384 + 256 + h * 32 + c];
        vs[j][c] = v;
    }
    __syncthreads();

    const float scale = 0.17677669529663687f;   // 32^-0.5

    // ---- S = scale * q @ k^T : 169 tiles of 4x4 ----
    if (tid < 169) {
        int ti = (tid / 13) * 4, tj = (tid % 13) * 4;
        float acc[4][4];
#pragma unroll
        for (int ii = 0; ii < 4; ii++)
#pragma unroll
            for (int jj = 0; jj < 4; jj++) acc[ii][jj] = 0.f;
#pragma unroll
        for (int c = 0; c < 32; c++) {
            float a[4], bb[4];
#pragma unroll
            for (int ii = 0; ii < 4; ii++) a[ii] = qs[ti + ii][c];
#pragma unroll
            for (int jj = 0; jj < 4; jj++) bb[jj] = ks[tj + jj][c];
#pragma unroll
            for (int ii = 0; ii < 4; ii++)
#pragma unroll
                for (int jj = 0; jj < 4; jj++) acc[ii][jj] += a[ii] * bb[jj];
        }
#pragma unroll
        for (int ii = 0; ii < 4; ii++)
#pragma unroll
            for (int jj = 0; jj < 4; jj++)
                S[(ti + ii) * 52 + tj + jj] = acc[ii][jj] * scale;
    }
    __syncthreads();

    // ---- softmax rows ----
    if (tid < 49) {
        float* row = S + tid * 52;
        float m = -1e30f;
        for (int j = 0; j < 49; j++) m = fmaxf(m, row[j]);
        float s = 0.f;
        for (int j = 0; j < 49; j++) {
            float e = __expf(row[j] - m);
            row[j] = e;
            s += e;
        }
        float inv = __fdividef(1.f, s);
        for (int j = 0; j < 49; j++) row[j] *= inv;
    }
    __syncthreads();

    // ---- O = P @ v (+ conv(v) + bias) : 13 x 8 tiles of 4x4 ----
    if (tid < 104) {
        int ti = (tid >> 3) * 4, td = (tid & 7) * 4;
        float acc[4][4];
#pragma unroll
        for (int ii = 0; ii < 4; ii++)
#pragma unroll
            for (int dd = 0; dd < 4; dd++) acc[ii][dd] = 0.f;
#pragma unroll
        for (int jy = 0; jy < 7; jy++)
#pragma unroll
            for (int jx = 0; jx < 7; jx++) {
                int j = jy * 7 + jx;
                const float* vp = &vs[(jy + 1) * 9 + jx + 1][td];
                float p[4], v[4];
#pragma unroll
                for (int ii = 0; ii < 4; ii++) p[ii] = S[(ti + ii) * 52 + j];
#pragma unroll
                for (int dd = 0; dd < 4; dd++) v[dd] = vp[dd];
#pragma unroll
                for (int ii = 0; ii < 4; ii++)
#pragma unroll
                    for (int dd = 0; dd < 4; dd++) acc[ii][dd] += p[ii] * v[dd];
            }
#pragma unroll
        for (int ii = 0; ii < 4; ii++) {
            int i = ti + ii;
            if (i < 49) {
                int iy = i / 7, ix = i % 7;
                int n = (Y0 + iy) * 56 + X0 + ix;
                size_t ob = ((size_t)b * N_ + n) * 128 + h * 32 + td;
#pragma unroll
                for (int dd = 0; dd < 4; dd++) {
                    int cc = td + dd;
                    float s = bl[cc];
                    const float* w = wl + cc * 9;
#pragma unroll
                    for (int dy = 0; dy < 3; dy++)
#pragma unroll
                        for (int dx = 0; dx < 3; dx++)
                            s += w[dy * 3 + dx] * vs[(iy + dy) * 9 + (ix + dx)][cc];
                    g_attn[ob + dd] = acc[ii][dd] + s;
                }
            }
        }
    }
}

// ============================================================================
extern "C" void kernel_launch(void* const* d_in, const int* in_sizes, int n_in,
                              void* d_out, int out_size)
{
    const float* x      = (const float*)d_in[0];
    const float* w_qkv  = (const float*)d_in[1];
    const float* w_lim  = (const float*)d_in[2];
    const float* b_lim  = (const float*)d_in[3];
    const float* w_proj = (const float*)d_in[4];
    const float* b_proj = (const float*)d_in[5];
    float* out = (float*)d_out;

    float *qkv_ptr, *attn_ptr;
    __nv_bfloat16 *wh_ptr, *wl_ptr;
    cudaGetSymbolAddress((void**)&qkv_ptr,  g_qkv);
    cudaGetSymbolAddress((void**)&attn_ptr, g_attn);
    cudaGetSymbolAddress((void**)&wh_ptr,   g_wh);
    cudaGetSymbolAddress((void**)&wl_ptr,   g_wl);

    cudaFuncSetAttribute(hmma_gemm, cudaFuncAttributeMaxDynamicSharedMemorySize, SM_BYTES);

    // 0) split weights into bf16 hi/lo
    prep_weights<<<(512 * 128 + 255) / 256, 256>>>(w_qkv, w_proj);

    // 1) qkv = x @ w_qkv^T  (A tile loaded once, 3 W tiles)
    hmma_gemm<<<M_TOT / 64, 256, SM_BYTES>>>(x, wh_ptr, wl_ptr, qkv_ptr, 384, 3, nullptr);

    // 2) fused windowed attention + depthwise conv + bias (per head)
    attn_fused<<<B_ * 64 * NHEAD, 224>>>(w_lim, b_lim);

    // 3) out = g_attn @ w_proj^T + b_proj
    hmma_gemm<<<M_TOT / 64, 256, SM_BYTES>>>(attn_ptr, wh_ptr + 384 * 128,
                                             wl_ptr + 384 * 128, out, 128, 1, b_proj);
}

// round 7
// speedup vs baseline: 1.1880x; 1.1844x over previous
#include <cuda_runtime.h>
#include <cuda_bf16.h>
#include <cstdint>

#define B_    64
#define Himg  56
#define Wimg  56
#define C_    128
#define N_    3136
#define NHEAD 4
#define M_TOT (B_ * N_)     // 200704

// Scratch (allocation-free rule: device globals)
__device__ float g_qkv[(size_t)M_TOT * 384];           // 308 MB
__device__ float g_attn[(size_t)M_TOT * C_];           // 103 MB
__device__ __nv_bfloat16 g_wh[512 * 128];              // weights hi (qkv rows 0..383, proj 384..511)
__device__ __nv_bfloat16 g_wl[512 * 128];              // weights lo

// ============================================================================
// Weight split prep: fp32 -> bf16 hi/lo
// ============================================================================
__global__ void prep_weights(const float* __restrict__ w_qkv,
                             const float* __restrict__ w_proj)
{
    int idx = blockIdx.x * 256 + threadIdx.x;
    if (idx >= 512 * 128) return;
    float w = (idx < 384 * 128) ? w_qkv[idx] : w_proj[idx - 384 * 128];
    __nv_bfloat16 hi = __float2bfloat16(w);
    float r = w - __bfloat162float(hi);
    g_wh[idx] = hi;
    g_wl[idx] = __float2bfloat16(r);
}

// ============================================================================
// HMMA GEMM (R3 config, measured-good): C[M, ldc] = A[M,128] @ W[N,128]^T.
// Tile 128x128, 256 threads (8 warps, 4x2), warp tile 32x64. 2D grid.
// ============================================================================
#define LDT 136                      // padded row stride in bf16 elements
#define TILE_B (128 * LDT * 2)       // 34816 B per tile
#define SM_AHI 0
#define SM_ALO (TILE_B)
#define SM_WHI (2 * TILE_B)
#define SM_WLO (3 * TILE_B)
#define SM_BYTES (4 * TILE_B)

__device__ __forceinline__ uint32_t smem_u32(const void* p) {
    uint32_t a;
    asm("{ .reg .u64 t; cvta.to.shared.u64 t, %1; cvt.u32.u64 %0, t; }" : "=r"(a) : "l"(p));
    return a;
}

__device__ __forceinline__ uint32_t pack2(float a, float b) {
    __nv_bfloat16 ha = __float2bfloat16(a), hb = __float2bfloat16(b);
    unsigned short ua = reinterpret_cast<unsigned short&>(ha);
    unsigned short ub = reinterpret_cast<unsigned short&>(hb);
    return (uint32_t)ua | ((uint32_t)ub << 16);
}

__device__ __forceinline__ void mma16816(float* d, const uint32_t* a, const uint32_t* b) {
    asm volatile(
        "mma.sync.aligned.m16n8k16.row.col.f32.bf16.bf16.f32 "
        "{%0,%1,%2,%3}, {%4,%5,%6,%7}, {%8,%9}, {%0,%1,%2,%3};"
        : "+f"(d[0]), "+f"(d[1]), "+f"(d[2]), "+f"(d[3])
        : "r"(a[0]), "r"(a[1]), "r"(a[2]), "r"(a[3]), "r"(b[0]), "r"(b[1]));
}

__global__ void __launch_bounds__(256)
hmma_gemm(const float* __restrict__ A,
          const __nv_bfloat16* __restrict__ whi,
          const __nv_bfloat16* __restrict__ wlo,
          float* __restrict__ C, int ldc,
          const float* __restrict__ bias)
{
    extern __shared__ char smem[];
    const uint32_t sb = smem_u32(smem);
    const int tid = threadIdx.x;
    const int wid = tid >> 5;
    const int lane = tid & 31;
    const int m0 = blockIdx.y * 128;
    const int n0 = blockIdx.x * 128;

    // ---- Load + split A tile (128 x 128 fp32 -> bf16 hi/lo) ----
#pragma unroll
    for (int it = 0; it < 8; it++) {
        int e = it * 256 + tid;
        int r = e >> 4;
        int k0 = (e & 15) * 8;
        const float4* p = reinterpret_cast<const float4*>(A + (size_t)(m0 + r) * 128 + k0);
        float4 x0 = p[0], x1 = p[1];
        float f[8] = {x0.x, x0.y, x0.z, x0.w, x1.x, x1.y, x1.z, x1.w};
        uint32_t h[4], l[4];
#pragma unroll
        for (int j = 0; j < 4; j++) {
            float a = f[2 * j], b = f[2 * j + 1];
            __nv_bfloat16 ha = __float2bfloat16(a), hb = __float2bfloat16(b);
            float ra = a - __bfloat162float(ha);
            float rb = b - __bfloat162float(hb);
            unsigned short ua = reinterpret_cast<unsigned short&>(ha);
            unsigned short ub = reinterpret_cast<unsigned short&>(hb);
            h[j] = (uint32_t)ua | ((uint32_t)ub << 16);
            l[j] = pack2(ra, rb);
        }
        uint32_t off = (uint32_t)(r * LDT + k0) * 2;
        *reinterpret_cast<uint4*>(smem + SM_AHI + off) = make_uint4(h[0], h[1], h[2], h[3]);
        *reinterpret_cast<uint4*>(smem + SM_ALO + off) = make_uint4(l[0], l[1], l[2], l[3]);
    }
    // ---- Load W tiles (already bf16) ----
#pragma unroll
    for (int it = 0; it < 8; it++) {
        int e = it * 256 + tid;
        int r = e >> 4;
        int k0 = (e & 15) * 8;
        uint32_t off = (uint32_t)(r * LDT + k0) * 2;
        *reinterpret_cast<uint4*>(smem + SM_WHI + off) =
            *reinterpret_cast<const uint4*>(whi + (size_t)(n0 + r) * 128 + k0);
        *reinterpret_cast<uint4*>(smem + SM_WLO + off) =
            *reinterpret_cast<const uint4*>(wlo + (size_t)(n0 + r) * 128 + k0);
    }
    __syncthreads();

    const int mrow = (wid & 3) * 32;
    const int ncol = (wid >> 2) * 64;
    const int grp = lane >> 2;
    const int thr4 = lane & 3;

    float acc[2][8][4];
#pragma unroll
    for (int mt = 0; mt < 2; mt++)
#pragma unroll
        for (int nt = 0; nt < 8; nt++)
#pragma unroll
            for (int j = 0; j < 4; j++) acc[mt][nt][j] = 0.f;

#pragma unroll
    for (int pass = 0; pass < 3; pass++) {
        const uint32_t sA = sb + ((pass == 2) ? SM_ALO : SM_AHI);
        const uint32_t sB = sb + ((pass == 1) ? SM_WLO : SM_WHI);
#pragma unroll
        for (int ks = 0; ks < 8; ks++) {
            const int k0 = ks * 16;
            uint32_t afr[2][4];
#pragma unroll
            for (int mt = 0; mt < 2; mt++) {
                int r = mrow + mt * 16 + grp;
                uint32_t base = sA + (uint32_t)(r * LDT + k0 + thr4 * 2) * 2;
                asm volatile("ld.shared.b32 %0, [%1];" : "=r"(afr[mt][0]) : "r"(base));
                asm volatile("ld.shared.b32 %0, [%1];" : "=r"(afr[mt][1]) : "r"(base + 8 * LDT * 2));
                asm volatile("ld.shared.b32 %0, [%1];" : "=r"(afr[mt][2]) : "r"(base + 16));
                asm volatile("ld.shared.b32 %0, [%1];" : "=r"(afr[mt][3]) : "r"(base + 8 * LDT * 2 + 16));
            }
#pragma unroll
            for (int nt = 0; nt < 8; nt++) {
                int n = ncol + nt * 8 + grp;
                uint32_t base = sB + (uint32_t)(n * LDT + k0 + thr4 * 2) * 2;
                uint32_t bfr[2];
                asm volatile("ld.shared.b32 %0, [%1];" : "=r"(bfr[0]) : "r"(base));
                asm volatile("ld.shared.b32 %0, [%1];" : "=r"(bfr[1]) : "r"(base + 16));
#pragma unroll
                for (int mt = 0; mt < 2; mt++)
                    mma16816(acc[mt][nt], afr[mt], bfr);
            }
        }
    }

    // ---- Epilogue ----
#pragma unroll
    for (int mt = 0; mt < 2; mt++) {
        int r0 = m0 + mrow + mt * 16 + grp;
#pragma unroll
        for (int nt = 0; nt < 8; nt++) {
            int c = n0 + ncol + nt * 8 + thr4 * 2;
            float bx = 0.f, by = 0.f;
            if (bias) { bx = bias[c]; by = bias[c + 1]; }
            float2 v0 = make_float2(acc[mt][nt][0] + bx, acc[mt][nt][1] + by);
            float2 v1 = make_float2(acc[mt][nt][2] + bx, acc[mt][nt][3] + by);
            *reinterpret_cast<float2*>(C + (size_t)r0 * ldc + c) = v0;
            *reinterpret_cast<float2*>(C + (size_t)(r0 + 8) * ldc + c) = v1;
        }
    }
}

// ============================================================================
// Windowed attention (R3 config, measured-good): one block per (b,win,head).
// ============================================================================
__global__ __launch_bounds__(224) void attn_kernel()
{
    const int idx = blockIdx.x;
    const int h = idx & 3;
    const int g = (idx >> 2) & 63;
    const int b = idx >> 8;
    const int gy = g >> 3, gx = g & 7;

    __shared__ float qs[52][33];
    __shared__ float ks[52][33];
    __shared__ float vs[52][33];
    __shared__ float S[52 * 52];

    const int tid = threadIdx.x;

    for (int l = tid; l < 49 * 32; l += 224) {
        int i = l >> 5, c = l & 31;
        int n = (gy * 7 + i / 7) * 56 + gx * 7 + (i % 7);
        size_t base = ((size_t)b * N_ + n) * 384 + h * 32 + c;
        qs[i][c] = g_qkv[base];
        ks[i][c] = g_qkv[base + 128];
        vs[i][c] = g_qkv[base + 256];
    }
    if (tid < 96) {
        int r = 49 + tid / 32, c = tid & 31;
        qs[r][c] = 0.f; ks[r][c] = 0.f; vs[r][c] = 0.f;
    }
    __syncthreads();

    const float scale = 0.17677669529663687f;   // 32^-0.5

    if (tid < 169) {
        int ti = (tid / 13) * 4, tj = (tid % 13) * 4;
        float acc[4][4];
#pragma unroll
        for (int ii = 0; ii < 4; ii++)
#pragma unroll
            for (int jj = 0; jj < 4; jj++) acc[ii][jj] = 0.f;
#pragma unroll
        for (int c = 0; c < 32; c++) {
            float a[4], bb[4];
#pragma unroll
            for (int ii = 0; ii < 4; ii++) a[ii] = qs[ti + ii][c];
#pragma unroll
            for (int jj = 0; jj < 4; jj++) bb[jj] = ks[tj + jj][c];
#pragma unroll
            for (int ii = 0; ii < 4; ii++)
#pragma unroll
                for (int jj = 0; jj < 4; jj++) acc[ii][jj] += a[ii] * bb[jj];
        }
#pragma unroll
        for (int ii = 0; ii < 4; ii++)
#pragma unroll
            for (int jj = 0; jj < 4; jj++)
                S[(ti + ii) * 52 + tj + jj] = acc[ii][jj] * scale;
    }
    __syncthreads();

    if (tid < 49) {
        float m = -1e30f;
        for (int j = 0; j < 49; j++) m = fmaxf(m, S[tid * 52 + j]);
        float s = 0.f;
        for (int j = 0; j < 49; j++) {
            float e = __expf(S[tid * 52 + j] - m);
            S[tid * 52 + j] = e;
            s += e;
        }
        float inv = __fdividef(1.f, s);
        for (int j = 0; j < 49; j++) S[tid * 52 + j] *= inv;
    }
    __syncthreads();

    if (tid < 104) {
        int ti = (tid >> 3) * 4, td = (tid & 7) * 4;
        float acc[4][4];
#pragma unroll
        for (int ii = 0; ii < 4; ii++)
#pragma unroll
            for (int dd = 0; dd < 4; dd++) acc[ii][dd] = 0.f;
        for (int j = 0; j < 49; j++) {
            float p[4], v[4];
#pragma unroll
            for (int ii = 0; ii < 4; ii++) p[ii] = S[(ti + ii) * 52 + j];
#pragma unroll
            for (int dd = 0; dd < 4; dd++) v[dd] = vs[j][td + dd];
#pragma unroll
            for (int ii = 0; ii < 4; ii++)
#pragma unroll
                for (int dd = 0; dd < 4; dd++) acc[ii][dd] += p[ii] * v[dd];
        }
#pragma unroll
        for (int ii = 0; ii < 4; ii++) {
            int i = ti + ii;
            if (i < 49) {
                int n = (gy * 7 + i / 7) * 56 + gx * 7 + (i % 7);
                size_t ob = ((size_t)b * N_ + n) * 128 + h * 32 + td;
#pragma unroll
                for (int dd = 0; dd < 4; dd++) g_attn[ob + dd] = acc[ii][dd];
            }
        }
    }
}

// ============================================================================
// Tiled depthwise 3x3 conv on V + bias, added in-place to g_attn.
// Block = (y-tile of 8 rows, 32-ch split, batch). 256 threads.
// v staged in smem with y-halo rows and zero x-pad columns (image boundary).
// ============================================================================
#define CONV_SMEM (10 * 58 * 32 * 4)   // 74240 B

__global__ __launch_bounds__(256) void conv_tiled(
    const float* __restrict__ w_lim, const float* __restrict__ b_lim)
{
    extern __shared__ float vsm[];     // [10 rows][58 x][32 ch]
    const int yt = blockIdx.x;         // 0..6
    const int c0 = blockIdx.y * 32;    // channel split
    const int b  = blockIdx.z;
    const int y0 = yt * 8;
    const int tid = threadIdx.x;
    const int ch = tid & 31;
    const int xg = tid >> 5;           // 0..7

    // zero the x-pad columns (x'=0 and x'=57), all 10 rows
    for (int l = tid; l < 640; l += 256) {
        int r = l / 64;
        int side = (l >> 5) & 1;
        int c = l & 31;
        vsm[(r * 58 + (side ? 57 : 0)) * 32 + c] = 0.f;
    }
    // load interior: rows y0-1..y0+8, x 0..55 (zero outside image in y)
    for (int l = tid; l < 10 * 56 * 32; l += 256) {
        int c = l & 31;
        int x = (l >> 5) % 56;
        int r = (l >> 5) / 56;
        int Y = y0 + r - 1;
        float v = 0.f;
        if ((unsigned)Y < 56u)
            v = g_qkv[((size_t)b * N_ + Y * 56 + x) * 384 + 256 + c0 + c];
        vsm[(r * 58 + x + 1) * 32 + c] = v;
    }

    // conv weights for this thread's channel (L1-broadcast across warp impossible
    // here since each lane has its own ch, but it's 10 coalesced-ish loads once)
    float w[9];
#pragma unroll
    for (int t = 0; t < 9; t++) w[t] = w_lim[(c0 + ch) * 9 + t];
    const float bias = b_lim[c0 + ch];

    __syncthreads();

    // each thread: rows 0..7, x in {xg, xg+8, ..., xg+48}
#pragma unroll
    for (int k = 0; k < 7; k++) {
        const int x = xg + 8 * k;
#pragma unroll
        for (int r = 0; r < 8; r++) {
            float s = bias;
#pragma unroll
            for (int dy = 0; dy < 3; dy++)
#pragma unroll
                for (int dx = 0; dx < 3; dx++)
                    s += w[dy * 3 + dx] * vsm[((r + dy) * 58 + x + dx) * 32 + ch];
            size_t o = ((size_t)b * N_ + (y0 + r) * 56 + x) * 128 + c0 + ch;
            g_attn[o] += s;
        }
    }
}

// ============================================================================
extern "C" void kernel_launch(void* const* d_in, const int* in_sizes, int n_in,
                              void* d_out, int out_size)
{
    const float* x      = (const float*)d_in[0];
    const float* w_qkv  = (const float*)d_in[1];
    const float* w_lim  = (const float*)d_in[2];
    const float* b_lim  = (const float*)d_in[3];
    const float* w_proj = (const float*)d_in[4];
    const float* b_proj = (const float*)d_in[5];
    float* out = (float*)d_out;

    float *qkv_ptr, *attn_ptr;
    __nv_bfloat16 *wh_ptr, *wl_ptr;
    cudaGetSymbolAddress((void**)&qkv_ptr,  g_qkv);
    cudaGetSymbolAddress((void**)&attn_ptr, g_attn);
    cudaGetSymbolAddress((void**)&wh_ptr,   g_wh);
    cudaGetSymbolAddress((void**)&wl_ptr,   g_wl);

    cudaFuncSetAttribute(hmma_gemm, cudaFuncAttributeMaxDynamicSharedMemorySize, SM_BYTES);
    cudaFuncSetAttribute(conv_tiled, cudaFuncAttributeMaxDynamicSharedMemorySize, CONV_SMEM);

    // 0) split weights into bf16 hi/lo
    prep_weights<<<(512 * 128 + 255) / 256, 256>>>(w_qkv, w_proj);

    // 1) qkv = x @ w_qkv^T   (R3 config: 2D grid)
    hmma_gemm<<<dim3(3, M_TOT / 128), 256, SM_BYTES>>>(x, wh_ptr, wl_ptr, qkv_ptr, 384, nullptr);

    // 2) windowed attention
    attn_kernel<<<B_ * 64 * NHEAD, 224>>>();

    // 3) tiled depthwise conv(v) + b_lim into g_attn
    conv_tiled<<<dim3(7, 4, B_), 256, CONV_SMEM>>>(w_lim, b_lim);

    // 4) out = g_attn @ w_proj^T + b_proj
    hmma_gemm<<<dim3(1, M_TOT / 128), 256, SM_BYTES>>>(attn_ptr, wh_ptr + 384 * 128,
                                                       wl_ptr + 384 * 128, out, 128, b_proj);
}

// round 8
// speedup vs baseline: 1.2245x; 1.0307x over previous
#include <cuda_runtime.h>
#include <cuda_bf16.h>
#include <cstdint>

#define B_    64
#define Himg  56
#define Wimg  56
#define C_    128
#define N_    3136
#define NHEAD 4
#define M_TOT (B_ * N_)     // 200704

// Scratch (allocation-free rule: device globals)
__device__ float g_qkv[(size_t)M_TOT * 384];           // 308 MB
__device__ float g_attn[(size_t)M_TOT * C_];           // 103 MB
__device__ __nv_bfloat16 g_wh[512 * 128];              // weights hi (qkv rows 0..383, proj 384..511)
__device__ __nv_bfloat16 g_wl[512 * 128];              // weights lo

// ============================================================================
// Weight split prep: fp32 -> bf16 hi/lo
// ============================================================================
__global__ void prep_weights(const float* __restrict__ w_qkv,
                             const float* __restrict__ w_proj)
{
    int idx = blockIdx.x * 256 + threadIdx.x;
    if (idx >= 512 * 128) return;
    float w = (idx < 384 * 128) ? w_qkv[idx] : w_proj[idx - 384 * 128];
    __nv_bfloat16 hi = __float2bfloat16(w);
    float r = w - __bfloat162float(hi);
    g_wh[idx] = hi;
    g_wl[idx] = __float2bfloat16(r);
}

// ============================================================================
// HMMA GEMM (R4 A-reuse config): C[M, ldc] = A[M,128] @ W[N,128]^T (+bias).
// Tile 128x128, 256 threads (8 warps, 4x2), warp tile 32x64.
// A tile loaded+split ONCE; loops over ntiles W tiles.
// ============================================================================
#define LDT 136                      // padded row stride in bf16 elements
#define TILE_B (128 * LDT * 2)       // 34816 B per tile
#define SM_AHI 0
#define SM_ALO (TILE_B)
#define SM_WHI (2 * TILE_B)
#define SM_WLO (3 * TILE_B)
#define SM_BYTES (4 * TILE_B)

__device__ __forceinline__ uint32_t smem_u32(const void* p) {
    uint32_t a;
    asm("{ .reg .u64 t; cvta.to.shared.u64 t, %1; cvt.u32.u64 %0, t; }" : "=r"(a) : "l"(p));
    return a;
}

__device__ __forceinline__ uint32_t pack2(float a, float b) {
    __nv_bfloat16 ha = __float2bfloat16(a), hb = __float2bfloat16(b);
    unsigned short ua = reinterpret_cast<unsigned short&>(ha);
    unsigned short ub = reinterpret_cast<unsigned short&>(hb);
    return (uint32_t)ua | ((uint32_t)ub << 16);
}

__device__ __forceinline__ void mma16816(float* d, const uint32_t* a, const uint32_t* b) {
    asm volatile(
        "mma.sync.aligned.m16n8k16.row.col.f32.bf16.bf16.f32 "
        "{%0,%1,%2,%3}, {%4,%5,%6,%7}, {%8,%9}, {%0,%1,%2,%3};"
        : "+f"(d[0]), "+f"(d[1]), "+f"(d[2]), "+f"(d[3])
        : "r"(a[0]), "r"(a[1]), "r"(a[2]), "r"(a[3]), "r"(b[0]), "r"(b[1]));
}

__global__ void __launch_bounds__(256)
hmma_gemm(const float* __restrict__ A,
          const __nv_bfloat16* __restrict__ whi,
          const __nv_bfloat16* __restrict__ wlo,
          float* __restrict__ C, int ldc, int ntiles,
          const float* __restrict__ bias)
{
    extern __shared__ char smem[];
    const uint32_t sb = smem_u32(smem);
    const int tid = threadIdx.x;
    const int wid = tid >> 5;
    const int lane = tid & 31;
    const int m0 = blockIdx.x * 128;

    // ---- Load + split A tile (128 x 128 fp32 -> bf16 hi/lo), once ----
#pragma unroll
    for (int it = 0; it < 8; it++) {
        int e = it * 256 + tid;
        int r = e >> 4;
        int k0 = (e & 15) * 8;
        const float4* p = reinterpret_cast<const float4*>(A + (size_t)(m0 + r) * 128 + k0);
        float4 x0 = p[0], x1 = p[1];
        float f[8] = {x0.x, x0.y, x0.z, x0.w, x1.x, x1.y, x1.z, x1.w};
        uint32_t h[4], l[4];
#pragma unroll
        for (int j = 0; j < 4; j++) {
            float a = f[2 * j], b = f[2 * j + 1];
            __nv_bfloat16 ha = __float2bfloat16(a), hb = __float2bfloat16(b);
            float ra = a - __bfloat162float(ha);
            float rb = b - __bfloat162float(hb);
            unsigned short ua = reinterpret_cast<unsigned short&>(ha);
            unsigned short ub = reinterpret_cast<unsigned short&>(hb);
            h[j] = (uint32_t)ua | ((uint32_t)ub << 16);
            l[j] = pack2(ra, rb);
        }
        uint32_t off = (uint32_t)(r * LDT + k0) * 2;
        *reinterpret_cast<uint4*>(smem + SM_AHI + off) = make_uint4(h[0], h[1], h[2], h[3]);
        *reinterpret_cast<uint4*>(smem + SM_ALO + off) = make_uint4(l[0], l[1], l[2], l[3]);
    }

    const int mrow = (wid & 3) * 32;
    const int ncol = (wid >> 2) * 64;
    const int grp = lane >> 2;
    const int thr4 = lane & 3;

    for (int nt = 0; nt < ntiles; nt++) {
        const int n0 = nt * 128;
        // ---- Load W tiles for this n block ----
#pragma unroll
        for (int it = 0; it < 8; it++) {
            int e = it * 256 + tid;
            int r = e >> 4;
            int k0 = (e & 15) * 8;
            uint32_t off = (uint32_t)(r * LDT + k0) * 2;
            *reinterpret_cast<uint4*>(smem + SM_WHI + off) =
                *reinterpret_cast<const uint4*>(whi + (size_t)(n0 + r) * 128 + k0);
            *reinterpret_cast<uint4*>(smem + SM_WLO + off) =
                *reinterpret_cast<const uint4*>(wlo + (size_t)(n0 + r) * 128 + k0);
        }
        __syncthreads();

        float acc[2][8][4];
#pragma unroll
        for (int mt = 0; mt < 2; mt++)
#pragma unroll
            for (int ntt = 0; ntt < 8; ntt++)
#pragma unroll
                for (int j = 0; j < 4; j++) acc[mt][ntt][j] = 0.f;

#pragma unroll
        for (int pass = 0; pass < 3; pass++) {
            const uint32_t sA = sb + ((pass == 2) ? SM_ALO : SM_AHI);
            const uint32_t sB = sb + ((pass == 1) ? SM_WLO : SM_WHI);
#pragma unroll
            for (int ks = 0; ks < 8; ks++) {
                const int k0 = ks * 16;
                uint32_t afr[2][4];
#pragma unroll
                for (int mt = 0; mt < 2; mt++) {
                    int r = mrow + mt * 16 + grp;
                    uint32_t base = sA + (uint32_t)(r * LDT + k0 + thr4 * 2) * 2;
                    asm volatile("ld.shared.b32 %0, [%1];" : "=r"(afr[mt][0]) : "r"(base));
                    asm volatile("ld.shared.b32 %0, [%1];" : "=r"(afr[mt][1]) : "r"(base + 8 * LDT * 2));
                    asm volatile("ld.shared.b32 %0, [%1];" : "=r"(afr[mt][2]) : "r"(base + 16));
                    asm volatile("ld.shared.b32 %0, [%1];" : "=r"(afr[mt][3]) : "r"(base + 8 * LDT * 2 + 16));
                }
#pragma unroll
                for (int ntt = 0; ntt < 8; ntt++) {
                    int n = ncol + ntt * 8 + grp;
                    uint32_t base = sB + (uint32_t)(n * LDT + k0 + thr4 * 2) * 2;
                    uint32_t bfr[2];
                    asm volatile("ld.shared.b32 %0, [%1];" : "=r"(bfr[0]) : "r"(base));
                    asm volatile("ld.shared.b32 %0, [%1];" : "=r"(bfr[1]) : "r"(base + 16));
#pragma unroll
                    for (int mt = 0; mt < 2; mt++)
                        mma16816(acc[mt][ntt], afr[mt], bfr);
                }
            }
        }

        // ---- Epilogue ----
#pragma unroll
        for (int mt = 0; mt < 2; mt++) {
            int r0 = m0 + mrow + mt * 16 + grp;
#pragma unroll
            for (int ntt = 0; ntt < 8; ntt++) {
                int c = n0 + ncol + ntt * 8 + thr4 * 2;
                float bx = 0.f, by = 0.f;
                if (bias) { bx = bias[c]; by = bias[c + 1]; }
                float2 v0 = make_float2(acc[mt][ntt][0] + bx, acc[mt][ntt][1] + by);
                float2 v1 = make_float2(acc[mt][ntt][2] + bx, acc[mt][ntt][3] + by);
                *reinterpret_cast<float2*>(C + (size_t)r0 * ldc + c) = v0;
                *reinterpret_cast<float2*>(C + (size_t)(r0 + 8) * ldc + c) = v1;
            }
        }
        __syncthreads();
    }
}

// ============================================================================
// Windowed attention (measured-good): one block per (b, window, head).
// ============================================================================
__global__ __launch_bounds__(224) void attn_kernel()
{
    const int idx = blockIdx.x;
    const int h = idx & 3;
    const int g = (idx >> 2) & 63;
    const int b = idx >> 8;
    const int gy = g >> 3, gx = g & 7;

    __shared__ float qs[52][33];
    __shared__ float ks[52][33];
    __shared__ float vs[52][33];
    __shared__ float S[52 * 52];

    const int tid = threadIdx.x;

    for (int l = tid; l < 49 * 32; l += 224) {
        int i = l >> 5, c = l & 31;
        int n = (gy * 7 + i / 7) * 56 + gx * 7 + (i % 7);
        size_t base = ((size_t)b * N_ + n) * 384 + h * 32 + c;
        qs[i][c] = g_qkv[base];
        ks[i][c] = g_qkv[base + 128];
        vs[i][c] = g_qkv[base + 256];
    }
    if (tid < 96) {
        int r = 49 + tid / 32, c = tid & 31;
        qs[r][c] = 0.f; ks[r][c] = 0.f; vs[r][c] = 0.f;
    }
    __syncthreads();

    const float scale = 0.17677669529663687f;   // 32^-0.5

    if (tid < 169) {
        int ti = (tid / 13) * 4, tj = (tid % 13) * 4;
        float acc[4][4];
#pragma unroll
        for (int ii = 0; ii < 4; ii++)
#pragma unroll
            for (int jj = 0; jj < 4; jj++) acc[ii][jj] = 0.f;
#pragma unroll
        for (int c = 0; c < 32; c++) {
            float a[4], bb[4];
#pragma unroll
            for (int ii = 0; ii < 4; ii++) a[ii] = qs[ti + ii][c];
#pragma unroll
            for (int jj = 0; jj < 4; jj++) bb[jj] = ks[tj + jj][c];
#pragma unroll
            for (int ii = 0; ii < 4; ii++)
#pragma unroll
                for (int jj = 0; jj < 4; jj++) acc[ii][jj] += a[ii] * bb[jj];
        }
#pragma unroll
        for (int ii = 0; ii < 4; ii++)
#pragma unroll
            for (int jj = 0; jj < 4; jj++)
                S[(ti + ii) * 52 + tj + jj] = acc[ii][jj] * scale;
    }
    __syncthreads();

    if (tid < 49) {
        float m = -1e30f;
        for (int j = 0; j < 49; j++) m = fmaxf(m, S[tid * 52 + j]);
        float s = 0.f;
        for (int j = 0; j < 49; j++) {
            float e = __expf(S[tid * 52 + j] - m);
            S[tid * 52 + j] = e;
            s += e;
        }
        float inv = __fdividef(1.f, s);
        for (int j = 0; j < 49; j++) S[tid * 52 + j] *= inv;
    }
    __syncthreads();

    if (tid < 104) {
        int ti = (tid >> 3) * 4, td = (tid & 7) * 4;
        float acc[4][4];
#pragma unroll
        for (int ii = 0; ii < 4; ii++)
#pragma unroll
            for (int dd = 0; dd < 4; dd++) acc[ii][dd] = 0.f;
        for (int j = 0; j < 49; j++) {
            float p[4], v[4];
#pragma unroll
            for (int ii = 0; ii < 4; ii++) p[ii] = S[(ti + ii) * 52 + j];
#pragma unroll
            for (int dd = 0; dd < 4; dd++) v[dd] = vs[j][td + dd];
#pragma unroll
            for (int ii = 0; ii < 4; ii++)
#pragma unroll
                for (int dd = 0; dd < 4; dd++) acc[ii][dd] += p[ii] * v[dd];
        }
#pragma unroll
        for (int ii = 0; ii < 4; ii++) {
            int i = ti + ii;
            if (i < 49) {
                int n = (gy * 7 + i / 7) * 56 + gx * 7 + (i % 7);
                size_t ob = ((size_t)b * N_ + n) * 128 + h * 32 + td;
#pragma unroll
                for (int dd = 0; dd < 4; dd++) g_attn[ob + dd] = acc[ii][dd];
            }
        }
    }
}

// ============================================================================
// Tiled depthwise 3x3 conv on V + bias, float4-vectorized, RMW into g_attn.
// Block = (y-tile of 8 rows, 32-ch split, batch). 256 threads.
// Thread owns 4 consecutive channels: 9 LDS.128 + LDG/STG.128 per output.
// ============================================================================
#define CONV_SMEM (10 * 58 * 32 * 4)   // 74240 B

__global__ __launch_bounds__(256) void conv_tiled(
    const float* __restrict__ w_lim, const float* __restrict__ b_lim)
{
    extern __shared__ float vsm[];     // [10 rows][58 x][32 ch]
    const int yt = blockIdx.x;         // 0..6
    const int c0 = blockIdx.y * 32;    // channel split
    const int b  = blockIdx.z;
    const int y0 = yt * 8;
    const int tid = threadIdx.x;

    // zero the x-pad columns (x'=0 and x'=57), all 10 rows
    for (int l = tid; l < 640; l += 256) {
        int r = l / 64;
        int side = (l >> 5) & 1;
        int c = l & 31;
        vsm[(r * 58 + (side ? 57 : 0)) * 32 + c] = 0.f;
    }
    // load interior: rows y0-1..y0+8, x 0..55 (zero outside image in y)
    for (int l = tid; l < 10 * 56 * 32; l += 256) {
        int c = l & 31;
        int x = (l >> 5) % 56;
        int r = (l >> 5) / 56;
        int Y = y0 + r - 1;
        float v = 0.f;
        if ((unsigned)Y < 56u)
            v = g_qkv[((size_t)b * N_ + Y * 56 + x) * 384 + 256 + c0 + c];
        vsm[(r * 58 + x + 1) * 32 + c] = v;
    }

    // compute mapping: thread -> (x-quarter group, 4-channel group)
    const int c4 = tid & 7;            // channel group: ch = c4*4
    const int xq = tid >> 3;           // 0..31
    const int ch = c4 * 4;

    // per-thread conv weights for 4 channels + bias (vector lanes)
    float4 w4[9];
#pragma unroll
    for (int t = 0; t < 9; t++) {
        w4[t].x = w_lim[(c0 + ch + 0) * 9 + t];
        w4[t].y = w_lim[(c0 + ch + 1) * 9 + t];
        w4[t].z = w_lim[(c0 + ch + 2) * 9 + t];
        w4[t].w = w_lim[(c0 + ch + 3) * 9 + t];
    }
    const float4 bias4 = *reinterpret_cast<const float4*>(b_lim + c0 + ch);

    __syncthreads();

    const float4* vsm4 = reinterpret_cast<const float4*>(vsm);

#pragma unroll
    for (int p = 0; p < 2; p++) {
        const int x = xq + 32 * p;
        if (x >= 56) break;
#pragma unroll
        for (int r = 0; r < 8; r++) {
            float4 acc = bias4;
#pragma unroll
            for (int dy = 0; dy < 3; dy++)
#pragma unroll
                for (int dx = 0; dx < 3; dx++) {
                    float4 v = vsm4[((r + dy) * 58 + x + dx) * 8 + c4];
                    float4 w = w4[dy * 3 + dx];
                    acc.x += w.x * v.x;
                    acc.y += w.y * v.y;
                    acc.z += w.z * v.z;
                    acc.w += w.w * v.w;
                }
            float4* ap = reinterpret_cast<float4*>(
                &g_attn[((size_t)b * N_ + (y0 + r) * 56 + x) * 128 + c0 + ch]);
            float4 o = *ap;
            o.x += acc.x; o.y += acc.y; o.z += acc.z; o.w += acc.w;
            *ap = o;
        }
    }
}

// ============================================================================
extern "C" void kernel_launch(void* const* d_in, const int* in_sizes, int n_in,
                              void* d_out, int out_size)
{
    const float* x      = (const float*)d_in[0];
    const float* w_qkv  = (const float*)d_in[1];
    const float* w_lim  = (const float*)d_in[2];
    const float* b_lim  = (const float*)d_in[3];
    const float* w_proj = (const float*)d_in[4];
    const float* b_proj = (const float*)d_in[5];
    float* out = (float*)d_out;

    float *qkv_ptr, *attn_ptr;
    __nv_bfloat16 *wh_ptr, *wl_ptr;
    cudaGetSymbolAddress((void**)&qkv_ptr,  g_qkv);
    cudaGetSymbolAddress((void**)&attn_ptr, g_attn);
    cudaGetSymbolAddress((void**)&wh_ptr,   g_wh);
    cudaGetSymbolAddress((void**)&wl_ptr,   g_wl);

    cudaFuncSetAttribute(hmma_gemm, cudaFuncAttributeMaxDynamicSharedMemorySize, SM_BYTES);
    cudaFuncSetAttribute(conv_tiled, cudaFuncAttributeMaxDynamicSharedMemorySize, CONV_SMEM);

    // 0) split weights into bf16 hi/lo
    prep_weights<<<(512 * 128 + 255) / 256, 256>>>(w_qkv, w_proj);

    // 1) qkv = x @ w_qkv^T  (A loaded+split once, 3 W tiles)
    hmma_gemm<<<M_TOT / 128, 256, SM_BYTES>>>(x, wh_ptr, wl_ptr, qkv_ptr, 384, 3, nullptr);

    // 2) windowed attention
    attn_kernel<<<B_ * 64 * NHEAD, 224>>>();

    // 3) tiled depthwise conv(v) + b_lim into g_attn (float4)
    conv_tiled<<<dim3(7, 4, B_), 256, CONV_SMEM>>>(w_lim, b_lim);

    // 4) out = g_attn @ w_proj^T + b_proj
    hmma_gemm<<<M_TOT / 128, 256, SM_BYTES>>>(attn_ptr, wh_ptr + 384 * 128,
                                              wl_ptr + 384 * 128, out, 128, 1, b_proj);
}